// round 6
// baseline (speedup 1.0000x reference)
#include <cuda_runtime.h>
#include <cuda_bf16.h>
#include <math.h>
#include <stdint.h>

// ---------------------------------------------------------------------------
// Problem constants
// ---------------------------------------------------------------------------
#define N_MP 2
#define B_SZ 1024
#define S_FAN 10
#define D_DIM 512
#define E_DIM 64
#define ATT_DIM 128
#define N_CLASSES 8
#define N_NODES 4096
#define N_EDGES 65536

#define N1_ROWS (B_SZ)            // 1024
#define N2_ROWS (B_SZ * S_FAN)    // 10240

// ---------------------------------------------------------------------------
// fp32 scratch arena
// ---------------------------------------------------------------------------
#define OFF_G0   0LL
#define SZ_G0    (2LL*1024*10)
#define OFF_G1   (OFF_G0 + SZ_G0)
#define SZ_G1    (2LL*10240*10)
#define OFF_G2   (OFF_G1 + SZ_G1)
#define SZ_G2    (2LL*1024*10)
#define OFF_QP   (OFF_G2 + SZ_G2)
#define SZ_QP    (2LL*4096*1024)
#define OFF_M1   (OFF_QP + SZ_QP)
#define SZ_M1    (2LL*10240*64)
#define OFF_R    (OFF_M1 + SZ_M1)
#define SZ_R     (2LL*1024*64)
#define OFF_TE   (OFF_R + SZ_R)
#define SZ_TE    (2LL*10240*64)
#define OFF_OUT  (OFF_TE + SZ_TE)
#define SZ_OUT   (2LL*1024*512)
#define OFF_ES   (OFF_OUT + SZ_OUT)
#define SZ_ES    (2LL*N_EDGES)
#define FARENA_TOTAL (OFF_ES + SZ_ES)

__device__ float g_scratch[FARENA_TOTAL];

// ---------------------------------------------------------------------------
// bf16 scratch arena (hi/lo operand planes)
// ---------------------------------------------------------------------------
#define BOFF_FHI   0LL
#define BSZ_F      (4096LL*512)
#define BOFF_FLO   (BOFF_FHI + BSZ_F)
#define BOFF_E0HI  (BOFF_FLO + BSZ_F)
#define BSZ_E0     (2LL*10240*64)
#define BOFF_E0LO  (BOFF_E0HI + BSZ_E0)
#define BOFF_H0HI  (BOFF_E0LO + BSZ_E0)
#define BSZ_H0     (2LL*1024*512)
#define BOFF_H0LO  (BOFF_H0HI + BSZ_H0)
#define BOFF_H1HI  (BOFF_H0LO + BSZ_H0)
#define BSZ_H1     (2LL*10240*512)
#define BOFF_H1LO  (BOFF_H1HI + BSZ_H1)
#define BOFF_X2HI  (BOFF_H1LO + BSZ_H1)
#define BSZ_X2     (2LL*1024*1024)
#define BOFF_X2LO  (BOFF_X2HI + BSZ_X2)
#define BOFF_WQPHI (BOFF_X2LO + BSZ_X2)
#define BSZ_WQP    (2LL*1024*512)
#define BOFF_WQPLO (BOFF_WQPHI + BSZ_WQP)
#define BOFF_WA1HI (BOFF_WQPLO + BSZ_WQP)
#define BSZ_WA1    (2LL*512*1024)
#define BOFF_WA1LO (BOFF_WA1HI + BSZ_WA1)
#define BOFF_WTEHI (BOFF_WA1LO + BSZ_WA1)
#define BSZ_WTE    (2LL*64*1088)
#define BOFF_WTELO (BOFF_WTEHI + BSZ_WTE)
#define BARENA_TOTAL (BOFF_WTELO + BSZ_WTE)

__device__ __nv_bfloat16 g_bscratch[BARENA_TOTAL];

// ---------------------------------------------------------------------------
// helpers
// ---------------------------------------------------------------------------
__device__ __forceinline__ uint32_t smem_u32(const void* p) {
    uint32_t a;
    asm("{ .reg .u64 t; cvta.to.shared.u64 t, %1; cvt.u32.u64 %0, t; }"
        : "=r"(a) : "l"(p));
    return a;
}

#define CP_ASYNC16(dst, src) \
    asm volatile("cp.async.cg.shared.global [%0], [%1], 16;" :: "r"(dst), "l"(src))
#define CP_COMMIT() asm volatile("cp.async.commit_group;")
#define CP_WAIT(n)  asm volatile("cp.async.wait_group %0;" :: "n"(n))

#define LDSM4(r, addr) \
    asm volatile("ldmatrix.sync.aligned.m8n8.x4.shared.b16 {%0,%1,%2,%3}, [%4];" \
        : "=r"((r)[0]), "=r"((r)[1]), "=r"((r)[2]), "=r"((r)[3]) : "r"(addr))
#define LDSM2(r, addr) \
    asm volatile("ldmatrix.sync.aligned.m8n8.x2.shared.b16 {%0,%1}, [%2];" \
        : "=r"((r)[0]), "=r"((r)[1]) : "r"(addr))

#define MMA_BF16(d, a, b) \
    asm volatile( \
        "mma.sync.aligned.m16n8k16.row.col.f32.bf16.bf16.f32 " \
        "{%0,%1,%2,%3}, {%4,%5,%6,%7}, {%8,%9}, {%0,%1,%2,%3};" \
        : "+f"((d)[0]), "+f"((d)[1]), "+f"((d)[2]), "+f"((d)[3]) \
        : "r"((a)[0]), "r"((a)[1]), "r"((a)[2]), "r"((a)[3]), \
          "r"((b)[0]), "r"((b)[1]))

__device__ __forceinline__ uint32_t pack2(float a, float b) {
    __nv_bfloat162 h = __floats2bfloat162_rn(a, b);
    return *(uint32_t*)&h;
}

__device__ __forceinline__ void split4(const float* v, float* h, float* l) {
#pragma unroll
    for (int i = 0; i < 4; i++) {
        h[i] = __bfloat162float(__float2bfloat16_rn(v[i]));
        l[i] = v[i] - h[i];
    }
}

__device__ __forceinline__ void store_split4(
    __nv_bfloat16* Ohi, __nv_bfloat16* Olo, long long base, const float* a)
{
    float h[4], l[4];
    split4(a, h, l);
    *(uint32_t*)(Ohi + base)     = pack2(h[0], h[1]);
    *(uint32_t*)(Ohi + base + 2) = pack2(h[2], h[3]);
    *(uint32_t*)(Olo + base)     = pack2(l[0], l[1]);
    *(uint32_t*)(Olo + base + 2) = pack2(l[2], l[3]);
}

// ---------------------------------------------------------------------------
// Weight transpose + bf16 hi/lo split.
// fold=0: W[sl][K][N] -> Wt[sl][N][K]
// fold=1: additionally fold K halves into N: out[(n + N*(k>=K/2))][k%(K/2)],
//         out ld = K/2 (used to merge the [x|agg] weight into one [2N,K/2]).
// ---------------------------------------------------------------------------
__global__ void transpose_split_kernel(
    const float* __restrict__ W, long long w_slice,
    __nv_bfloat16* __restrict__ Whi, __nv_bfloat16* __restrict__ Wlo,
    long long wt_slice, int K, int N, int fold)
{
    __shared__ float t[32][33];
    int sl = blockIdx.z;
    const float* Wp = W + (long long)sl * w_slice;
    int k0 = blockIdx.x * 32, n0 = blockIdx.y * 32;
    for (int r = threadIdx.y; r < 32; r += 8)
        t[r][threadIdx.x] = Wp[(long long)(k0 + r) * N + n0 + threadIdx.x];
    __syncthreads();
    __nv_bfloat16* ho = Whi + (long long)sl * wt_slice;
    __nv_bfloat16* lo = Wlo + (long long)sl * wt_slice;
    int khalf = K >> 1;
    for (int r = threadIdx.y; r < 32; r += 8) {
        float v = t[threadIdx.x][r];          // W[k0+tx][n0+r]
        int k = k0 + threadIdx.x, n = n0 + r;
        long long o;
        if (fold) {
            int hi = (k >= khalf) ? 1 : 0;
            o = (long long)(n + hi * N) * khalf + (k - hi * khalf);
        } else {
            o = (long long)n * K + k;
        }
        float h = __bfloat162float(__float2bfloat16_rn(v));
        ho[o] = __float2bfloat16_rn(h);
        lo[o] = __float2bfloat16_rn(v - h);
    }
}

// ---------------------------------------------------------------------------
// feats rows -> bf16 hi/lo planes (512 cols)
// ---------------------------------------------------------------------------
__global__ void split_rows_kernel(
    const float* __restrict__ src,
    __nv_bfloat16* __restrict__ Ohi, __nv_bfloat16* __restrict__ Olo)
{
    int row = blockIdx.x, t = threadIdx.x;
    float4 v = ((const float4*)(src + (long long)row * D_DIM))[t];
    float a[4] = {v.x, v.y, v.z, v.w};
    store_split4(Ohi, Olo, (long long)row * D_DIM + t * 4, a);
}

// ---------------------------------------------------------------------------
// Per-edge gate scores ES[mp][e] = edge_emb[e] · v_gate[mp,0]
// 8 warps / block, one warp per edge.
// ---------------------------------------------------------------------------
__global__ void edge_score_kernel(
    const float* __restrict__ edge_emb,
    const float* __restrict__ vg, long long vg_mp,
    float* __restrict__ ES)
{
    int e = blockIdx.x * 8 + (threadIdx.x >> 5);
    int lane = threadIdx.x & 31;
    const float* er = edge_emb + (long long)e * E_DIM;
    float e0 = er[lane], e1 = er[lane + 32];
#pragma unroll
    for (int mp = 0; mp < N_MP; mp++) {
        const float* vgp = vg + (long long)mp * vg_mp;
        float p = e0 * vgp[lane] + e1 * vgp[lane + 32];
#pragma unroll
        for (int off = 16; off; off >>= 1)
            p += __shfl_xor_sync(0xffffffffu, p, off);
        if (lane == 0) ES[(long long)mp * N_EDGES + e] = p;
    }
}

// ---------------------------------------------------------------------------
// Hop-1 gating: one warp per row; also stores gathered E0 rows as bf16 planes.
// ---------------------------------------------------------------------------
__global__ void edge_gate_kernel(
    const int* __restrict__ src_ids,
    const int* __restrict__ nb_ids,  long long nb_mp,
    const int* __restrict__ adjs,
    const float* __restrict__ edge_emb,
    const float* __restrict__ vg, long long vg_mp,
    float* __restrict__ gate_out, long long gate_mp,
    __nv_bfloat16* __restrict__ e_hi, __nv_bfloat16* __restrict__ e_lo,
    long long e_mp, int n_rows)
{
    int mp   = blockIdx.y;
    int warp = threadIdx.x >> 5;
    int lane = threadIdx.x & 31;
    int row  = blockIdx.x * (blockDim.x >> 5) + warp;
    if (row >= n_rows) return;

    const float* vgp = vg + (long long)mp * vg_mp;
    float v0 = vgp[lane], v1 = vgp[lane + 32];
    int srcn = src_ids[row];

    float scores[S_FAN];
#pragma unroll
    for (int s = 0; s < S_FAN; s++) {
        int nb = nb_ids[(long long)mp * nb_mp + (long long)row * S_FAN + s];
        int eid = adjs[(long long)srcn * N_NODES + nb];
        const float* er = edge_emb + (long long)eid * E_DIM;
        float e0 = er[lane], e1 = er[lane + 32];
        long long eo = (long long)mp * e_mp + ((long long)row * S_FAN + s) * E_DIM;
        __nv_bfloat16 h0 = __float2bfloat16_rn(e0);
        __nv_bfloat16 h1 = __float2bfloat16_rn(e1);
        e_hi[eo + lane]      = h0;
        e_hi[eo + lane + 32] = h1;
        e_lo[eo + lane]      = __float2bfloat16_rn(e0 - __bfloat162float(h0));
        e_lo[eo + lane + 32] = __float2bfloat16_rn(e1 - __bfloat162float(h1));
        float p = e0 * v0 + e1 * v1;
#pragma unroll
        for (int off = 16; off; off >>= 1)
            p += __shfl_xor_sync(0xffffffffu, p, off);
        scores[s] = p;
    }
    float m = scores[0];
#pragma unroll
    for (int s = 1; s < S_FAN; s++) m = fmaxf(m, scores[s]);
    float sum = 0.f;
#pragma unroll
    for (int s = 0; s < S_FAN; s++) { scores[s] = expf(scores[s] - m); sum += scores[s]; }
    float inv = 1.f / sum;
    float* go = gate_out + (long long)mp * gate_mp + (long long)row * S_FAN;
#pragma unroll
    for (int s = 0; s < S_FAN; s++)
        if (lane == s) go[s] = scores[s] * inv;
}

// ---------------------------------------------------------------------------
// Hop-2 gating via precomputed ES: one THREAD per row.
// ---------------------------------------------------------------------------
__global__ void gate2_kernel(
    const int* __restrict__ n1, long long n1_mp,
    const int* __restrict__ n2, long long n2_mp,
    const int* __restrict__ adjs,
    const float* __restrict__ ES,
    float* __restrict__ G1, long long g_mp)
{
    int mp = blockIdx.y;
    int r = blockIdx.x * 256 + threadIdx.x;
    if (r >= N2_ROWS) return;
    int src = n1[(long long)mp * n1_mp + r];
    const int* nbp = n2 + (long long)mp * n2_mp + (long long)r * S_FAN;
    const float* esp = ES + (long long)mp * N_EDGES;
    const int* arow = adjs + (long long)src * N_NODES;
    float sc[S_FAN];
#pragma unroll
    for (int s = 0; s < S_FAN; s++)
        sc[s] = esp[arow[nbp[s]]];
    float m = sc[0];
#pragma unroll
    for (int s = 1; s < S_FAN; s++) m = fmaxf(m, sc[s]);
    float sum = 0.f;
#pragma unroll
    for (int s = 0; s < S_FAN; s++) { sc[s] = expf(sc[s] - m); sum += sc[s]; }
    float inv = 1.f / sum;
    float* go = G1 + (long long)mp * g_mp + (long long)r * S_FAN;
#pragma unroll
    for (int s = 0; s < S_FAN; s++) go[s] = sc[s] * inv;
}

// ---------------------------------------------------------------------------
// General bf16 3-pass GEMM. C = [relu](A@B^T [+ bias])
// BM=128, BK=32, 256 threads, double buffered cp.async.
// ---------------------------------------------------------------------------
template<int BN>
__global__ __launch_bounds__(256)
void bf16_gemm(
    const __nv_bfloat16* __restrict__ Ahi, const __nv_bfloat16* __restrict__ Alo,
    long long A_mp, int lda,
    const __nv_bfloat16* __restrict__ Bhi, const __nv_bfloat16* __restrict__ Blo,
    long long B_mp, int ldb,
    const float* __restrict__ bias, long long bias_mp,
    float* __restrict__ C, long long C_mp, int ldc,
    int K)
{
    constexpr int BM = 128, BK = 32;
    constexpr int LDS = 40;
    constexpr int A_MAT = BM * LDS;
    constexpr int B_MAT = BN * LDS;
    constexpr int STAGE = 2 * A_MAT + 2 * B_MAT;
    constexpr int MT = 4;
    constexpr int NT = BN / 32;
    constexpr uint32_t OFF_ALO = A_MAT * 2;
    constexpr uint32_t OFF_BHI = 2 * A_MAT * 2;

    extern __shared__ __nv_bfloat16 smem[];
    uint32_t sbase0 = smem_u32(smem);

    int tid  = threadIdx.x;
    int wid  = tid >> 5;
    int lane = tid & 31;
    int wm   = wid >> 2;
    int wn   = wid & 3;
    int mp   = blockIdx.z;

    const __nv_bfloat16* Ahp = Ahi + (long long)mp * A_mp + (long long)blockIdx.y * BM * lda;
    const __nv_bfloat16* Alp = Alo + (long long)mp * A_mp + (long long)blockIdx.y * BM * lda;
    const __nv_bfloat16* Bhp = Bhi + (long long)mp * B_mp + (long long)blockIdx.x * BN * ldb;
    const __nv_bfloat16* Blp = Blo + (long long)mp * B_mp + (long long)blockIdx.x * BN * ldb;

    const int NKB = K / BK;

    auto issue = [&](int kb, int s) {
        int k0 = kb * BK;
        uint32_t sb = sbase0 + (uint32_t)s * STAGE * 2u;
#pragma unroll
        for (int i = 0; i < (BM * 4) / 256; i++) {
            int c = tid + i * 256;
            int row = c >> 2, ch = c & 3;
            long long g = (long long)row * lda + k0 + ch * 8;
            uint32_t d = sb + (uint32_t)(row * 80 + ch * 16);
            CP_ASYNC16(d, Ahp + g);
            CP_ASYNC16(d + OFF_ALO, Alp + g);
        }
#pragma unroll
        for (int i = 0; i < (BN * 4) / 256; i++) {
            int c = tid + i * 256;
            int row = c >> 2, ch = c & 3;
            long long g = (long long)row * ldb + k0 + ch * 8;
            uint32_t d = sb + OFF_BHI + (uint32_t)(row * 80 + ch * 16);
            CP_ASYNC16(d, Bhp + g);
            CP_ASYNC16(d + (uint32_t)(B_MAT * 2), Blp + g);
        }
        CP_COMMIT();
    };

    float acc[MT][NT][4];
#pragma unroll
    for (int i = 0; i < MT; i++)
#pragma unroll
        for (int j = 0; j < NT; j++)
#pragma unroll
            for (int q = 0; q < 4; q++) acc[i][j][q] = 0.f;

    issue(0, 0);

    for (int kb = 0; kb < NKB; kb++) {
        int s = kb & 1;
        if (kb + 1 < NKB) { issue(kb + 1, s ^ 1); CP_WAIT(1); }
        else              { CP_WAIT(0); }
        __syncthreads();

        uint32_t sA = sbase0 + (uint32_t)s * STAGE * 2u;
#pragma unroll
        for (int ks = 0; ks < 2; ks++) {
            uint32_t a_hi[MT][4], a_lo[MT][4];
#pragma unroll
            for (int mi = 0; mi < MT; mi++) {
                int r = wm * 64 + mi * 16 + (lane & 15);
                uint32_t ad = sA + (uint32_t)(r * 80 + ks * 32 + ((lane >> 4) << 4));
                LDSM4(a_hi[mi], ad);
                LDSM4(a_lo[mi], ad + OFF_ALO);
            }
            uint32_t b_hi[NT][2], b_lo[NT][2];
#pragma unroll
            for (int ni = 0; ni < NT; ni++) {
                int r = wn * (BN / 4) + ni * 8 + (lane & 7);
                uint32_t bd = sA + OFF_BHI +
                              (uint32_t)(r * 80 + ks * 32 + (((lane >> 3) & 1) << 4));
                LDSM2(b_hi[ni], bd);
                LDSM2(b_lo[ni], bd + (uint32_t)(B_MAT * 2));
            }
#pragma unroll
            for (int mi = 0; mi < MT; mi++)
#pragma unroll
                for (int ni = 0; ni < NT; ni++) {
                    MMA_BF16(acc[mi][ni], a_hi[mi], b_hi[ni]);
                    MMA_BF16(acc[mi][ni], a_hi[mi], b_lo[ni]);
                    MMA_BF16(acc[mi][ni], a_lo[mi], b_hi[ni]);
                }
        }
        __syncthreads();
    }

    float* Cp = C + (long long)mp * C_mp;
    const float* bp = bias ? bias + (long long)mp * bias_mp : nullptr;
    int mrow0 = blockIdx.y * BM + wm * 64;
#pragma unroll
    for (int mi = 0; mi < MT; mi++) {
#pragma unroll
        for (int ni = 0; ni < NT; ni++) {
            int col = blockIdx.x * BN + wn * (BN / 4) + ni * 8 + (lane & 3) * 2;
            int r0 = mrow0 + mi * 16 + (lane >> 2);
            float v0 = acc[mi][ni][0], v1 = acc[mi][ni][1];
            float v2 = acc[mi][ni][2], v3 = acc[mi][ni][3];
            if (bp) {
                float b0 = __ldg(bp + col), b1 = __ldg(bp + col + 1);
                v0 = fmaxf(v0 + b0, 0.f); v1 = fmaxf(v1 + b1, 0.f);
                v2 = fmaxf(v2 + b0, 0.f); v3 = fmaxf(v3 + b1, 0.f);
            }
            Cp[(long long)r0 * ldc + col]           = v0;
            Cp[(long long)r0 * ldc + col + 1]       = v1;
            Cp[(long long)(r0 + 8) * ldc + col]     = v2;
            Cp[(long long)(r0 + 8) * ldc + col + 1] = v3;
        }
    }
}

// ---------------------------------------------------------------------------
// Combine: H[row] = relu(Q[sel[row]] + sum_s g[row,s] * P[nb[row,s]] + bias)
// Q,P are columns [0,512) and [512,1024) of the merged QP matrix (ld=1024).
// ---------------------------------------------------------------------------
__global__ void combine_kernel(
    const float* __restrict__ QP, long long qp_mp,
    const int* __restrict__ sel, long long sel_mp,
    const int* __restrict__ nb, long long nb_mp,
    const float* __restrict__ gate, long long gate_mp,
    const float* __restrict__ bias, long long bias_mp,
    __nv_bfloat16* __restrict__ Ohi, __nv_bfloat16* __restrict__ Olo,
    long long o_mp)
{
    int mp = blockIdx.y, row = blockIdx.x, t = threadIdx.x;
    const float* Qp = QP + (long long)mp * qp_mp;
    const float* Pp = Qp + D_DIM;
    int sid = sel[(long long)mp * sel_mp + row];
    float4 q = ((const float4*)(Qp + (long long)sid * 1024))[t];
    float a[4] = {q.x, q.y, q.z, q.w};
    const float* gp = gate + (long long)mp * gate_mp + (long long)row * S_FAN;
    const int* nbp = nb + (long long)mp * nb_mp + (long long)row * S_FAN;
#pragma unroll
    for (int s = 0; s < S_FAN; s++) {
        float w = gp[s];
        int idx = nbp[s];
        float4 v = ((const float4*)(Pp + (long long)idx * 1024))[t];
        a[0] = fmaf(w, v.x, a[0]);
        a[1] = fmaf(w, v.y, a[1]);
        a[2] = fmaf(w, v.z, a[2]);
        a[3] = fmaf(w, v.w, a[3]);
    }
    float4 b = ((const float4*)(bias + (long long)mp * bias_mp))[t];
    a[0] = fmaxf(a[0] + b.x, 0.f);
    a[1] = fmaxf(a[1] + b.y, 0.f);
    a[2] = fmaxf(a[2] + b.z, 0.f);
    a[3] = fmaxf(a[3] + b.w, 0.f);
    store_split4(Ohi, Olo, (long long)mp * o_mp + (long long)row * D_DIM + t * 4, a);
}

// ---------------------------------------------------------------------------
// Layer-1 gate scores from edge-update partials. One warp per output row.
// ---------------------------------------------------------------------------
__global__ void scores_kernel(
    const float* __restrict__ R, long long r_mp,
    const float* __restrict__ M1, long long m_mp,
    const float* __restrict__ TE, long long te_mp,
    const float* __restrict__ be, long long be_mp,
    const float* __restrict__ vg, long long vg_mp,
    float* __restrict__ G2, long long g_mp)
{
    int mp = blockIdx.y;
    int warp = threadIdx.x >> 5, lane = threadIdx.x & 31;
    int r = blockIdx.x * 4 + warp;

    const float* vgp = vg + (long long)mp * vg_mp;
    float v0 = vgp[lane], v1 = vgp[lane + 32];
    float b0 = be[(long long)mp * be_mp + lane];
    float b1 = be[(long long)mp * be_mp + lane + 32];
    float r0 = R[(long long)mp * r_mp + (long long)r * E_DIM + lane];
    float r1 = R[(long long)mp * r_mp + (long long)r * E_DIM + lane + 32];

    float sc[S_FAN];
#pragma unroll
    for (int s = 0; s < S_FAN; s++) {
        long long i = (long long)r * S_FAN + s;
        float a0 = r0 + M1[(long long)mp * m_mp + i * E_DIM + lane]
                      + TE[(long long)mp * te_mp + i * E_DIM + lane] + b0;
        float a1 = r1 + M1[(long long)mp * m_mp + i * E_DIM + lane + 32]
                      + TE[(long long)mp * te_mp + i * E_DIM + lane + 32] + b1;
        float p = fmaxf(a0, 0.f) * v0 + fmaxf(a1, 0.f) * v1;
#pragma unroll
        for (int off = 16; off; off >>= 1)
            p += __shfl_xor_sync(0xffffffffu, p, off);
        sc[s] = p;
    }
    float m = sc[0];
#pragma unroll
    for (int s = 1; s < S_FAN; s++) m = fmaxf(m, sc[s]);
    float sum = 0.f;
#pragma unroll
    for (int s = 0; s < S_FAN; s++) { sc[s] = expf(sc[s] - m); sum += sc[s]; }
    float inv = 1.f / sum;
    float* go = G2 + (long long)mp * g_mp + (long long)r * S_FAN;
#pragma unroll
    for (int s = 0; s < S_FAN; s++)
        if (lane == s) go[s] = sc[s] * inv;
}

// ---------------------------------------------------------------------------
// Build X2 planes: [H0 | gate-weighted sum of H1]
// ---------------------------------------------------------------------------
__global__ void build_x2_kernel(
    const __nv_bfloat16* __restrict__ H0hi, const __nv_bfloat16* __restrict__ H0lo,
    long long h0_mp,
    const __nv_bfloat16* __restrict__ H1hi, const __nv_bfloat16* __restrict__ H1lo,
    long long h1_mp,
    const float* __restrict__ G2, long long g_mp,
    __nv_bfloat16* __restrict__ Xhi, __nv_bfloat16* __restrict__ Xlo,
    long long x_mp)
{
    int mp = blockIdx.y, r = blockIdx.x, t = threadIdx.x;
    long long hb = (long long)mp * h0_mp + (long long)r * D_DIM + t * 4;
    long long xb = (long long)mp * x_mp + (long long)r * (2 * D_DIM) + t * 4;
    *(uint2*)(Xhi + xb) = *(const uint2*)(H0hi + hb);
    *(uint2*)(Xlo + xb) = *(const uint2*)(H0lo + hb);

    const float* gp = G2 + (long long)mp * g_mp + (long long)r * S_FAN;
    float a[4] = {0.f, 0.f, 0.f, 0.f};
#pragma unroll
    for (int s = 0; s < S_FAN; s++) {
        float w = gp[s];
        long long p = (long long)mp * h1_mp + ((long long)r * S_FAN + s) * D_DIM + t * 4;
        uint2 uh = *(const uint2*)(H1hi + p);
        uint2 ul = *(const uint2*)(H1lo + p);
        float2 h0 = __bfloat1622float2(*(__nv_bfloat162*)&uh.x);
        float2 h1 = __bfloat1622float2(*(__nv_bfloat162*)&uh.y);
        float2 l0 = __bfloat1622float2(*(__nv_bfloat162*)&ul.x);
        float2 l1 = __bfloat1622float2(*(__nv_bfloat162*)&ul.y);
        a[0] = fmaf(w, h0.x + l0.x, a[0]);
        a[1] = fmaf(w, h0.y + l0.y, a[1]);
        a[2] = fmaf(w, h1.x + l1.x, a[2]);
        a[3] = fmaf(w, h1.y + l1.y, a[3]);
    }
    store_split4(Xhi, Xlo, xb + D_DIM, a);
}

// ---------------------------------------------------------------------------
// Fused metapath attention + softmax + FC.
// Block handles 16 batch items (32 OUT rows). Wa cached in smem K-tiles.
// dynamic smem: srow 32*512 + swa 8192 floats = 96 KB.
// ---------------------------------------------------------------------------
__global__ __launch_bounds__(256)
void att_final_kernel(
    const float* __restrict__ OUTB,
    const float* __restrict__ Wa, const float* __restrict__ ba,
    const float* __restrict__ va,
    const float* __restrict__ W_fc, const float* __restrict__ b_fc,
    float* __restrict__ out)
{
    extern __shared__ float sm[];
    float* srow = sm;               // 32 rows x 512
    float* swa  = sm + 32 * 512;    // 8192 floats: Wa tile / satt / agg
    __shared__ float s_att[32];

    int tid = threadIdx.x;
    int j = tid & 127, g = tid >> 7;
    int b0 = blockIdx.x * 16;

    // load 32 OUT rows (r = mp*16 + bi)
    for (int i = tid; i < 32 * 128; i += 256) {
        int r = i >> 7, c = i & 127;
        int mp = r >> 4, bi = r & 15;
        ((float4*)srow)[r * 128 + c] =
            ((const float4*)(OUTB + ((long long)mp * B_SZ + b0 + bi) * D_DIM))[c];
    }

    float acc[16];
#pragma unroll
    for (int i = 0; i < 16; i++) acc[i] = 0.f;

    for (int kt = 0; kt < 8; kt++) {
        __syncthreads();
        for (int i = tid; i < 64 * 32; i += 256)
            ((float4*)swa)[i] = ((const float4*)(Wa + (long long)kt * 64 * ATT_DIM))[i];
        __syncthreads();
#pragma unroll 4
        for (int k = 0; k < 64; k++) {
            float w = swa[k * 128 + j];
            int kk = kt * 64 + k;
#pragma unroll
            for (int i = 0; i < 16; i++)
                acc[i] = fmaf(srow[(g * 16 + i) * 512 + kk], w, acc[i]);
        }
    }
    __syncthreads();
    // satt[r][j] = tanh(acc + ba)*va  (reuse swa)
    float baj = ba[j], vaj = va[j];
#pragma unroll
    for (int i = 0; i < 16; i++)
        swa[(g * 16 + i) * 128 + j] = tanhf(acc[i] + baj) * vaj;
    __syncthreads();
    // reduce 128 -> att per row; 8 warps x 4 rows
    int wid = tid >> 5, lane = tid & 31;
#pragma unroll
    for (int q = 0; q < 4; q++) {
        int r = wid * 4 + q;
        float s = swa[r * 128 + lane] + swa[r * 128 + lane + 32]
                + swa[r * 128 + lane + 64] + swa[r * 128 + lane + 96];
#pragma unroll
        for (int off = 16; off; off >>= 1)
            s += __shfl_xor_sync(0xffffffffu, s, off);
        if (lane == 0) s_att[r] = s;
    }
    __syncthreads();
    // agg[bi][:] = w0*row_mp0 + w1*row_mp1  (into swa region, 16x512)
    for (int i = tid; i < 16 * 128; i += 256) {
        int bi = i >> 7, c = i & 127;
        float a0 = s_att[bi], a1 = s_att[16 + bi];
        float m = fmaxf(a0, a1);
        float e0 = expf(a0 - m), e1 = expf(a1 - m);
        float inv = 1.f / (e0 + e1);
        float w0 = e0 * inv, w1 = e1 * inv;
        float4 v0 = ((float4*)srow)[bi * 128 + c];
        float4 v1 = ((float4*)srow)[(16 + bi) * 128 + c];
        float4 rr;
        rr.x = w0 * v0.x + w1 * v1.x;
        rr.y = w0 * v0.y + w1 * v1.y;
        rr.z = w0 * v0.z + w1 * v1.z;
        rr.w = w0 * v0.w + w1 * v1.w;
        ((float4*)swa)[i] = rr;
    }
    __syncthreads();
    // FC: 16 b x 8 classes
    if (tid < 128) {
        int bi = tid >> 3, c = tid & 7;
        float s = 0.f;
#pragma unroll 8
        for (int k = 0; k < D_DIM; k++)
            s = fmaf(swa[bi * 512 + k], __ldg(W_fc + k * N_CLASSES + c), s);
        out[(b0 + bi) * N_CLASSES + c] = fmaxf(s + b_fc[c], 0.f);
    }
}

// ---------------------------------------------------------------------------
// Launch
// ---------------------------------------------------------------------------
extern "C" void kernel_launch(void* const* d_in, const int* in_sizes, int n_in,
                              void* d_out, int out_size)
{
    const int*   ids      = (const int*)d_in[0];
    const float* feats    = (const float*)d_in[1];
    const int*   adjs     = (const int*)d_in[2];
    const float* edge_emb = (const float*)d_in[3];
    const int*   n1       = (const int*)d_in[4];
    const int*   n2       = (const int*)d_in[5];
    const float* W_agg    = (const float*)d_in[6];
    const float* b_agg    = (const float*)d_in[7];
    const float* v_gate   = (const float*)d_in[8];
    const float* W_edge   = (const float*)d_in[9];
    const float* b_edge   = (const float*)d_in[10];
    const float* Wa       = (const float*)d_in[11];
    const float* ba       = (const float*)d_in[12];
    const float* va       = (const float*)d_in[13];
    const float* W_fc     = (const float*)d_in[14];
    const float* b_fc     = (const float*)d_in[15];
    float* out = (float*)d_out;

    float* S;
    cudaGetSymbolAddress((void**)&S, g_scratch);
    __nv_bfloat16* BS;
    cudaGetSymbolAddress((void**)&BS, g_bscratch);

    float* G0   = S + OFF_G0;
    float* G1   = S + OFF_G1;
    float* G2   = S + OFF_G2;
    float* QP   = S + OFF_QP;
    float* M1   = S + OFF_M1;
    float* R    = S + OFF_R;
    float* TE   = S + OFF_TE;
    float* OUTB = S + OFF_OUT;
    float* ES   = S + OFF_ES;

    __nv_bfloat16* FHI   = BS + BOFF_FHI;
    __nv_bfloat16* FLO   = BS + BOFF_FLO;
    __nv_bfloat16* E0HI  = BS + BOFF_E0HI;
    __nv_bfloat16* E0LO  = BS + BOFF_E0LO;
    __nv_bfloat16* H0HI  = BS + BOFF_H0HI;
    __nv_bfloat16* H0LO  = BS + BOFF_H0LO;
    __nv_bfloat16* H1HI  = BS + BOFF_H1HI;
    __nv_bfloat16* H1LO  = BS + BOFF_H1LO;
    __nv_bfloat16* X2HI  = BS + BOFF_X2HI;
    __nv_bfloat16* X2LO  = BS + BOFF_X2LO;
    __nv_bfloat16* WQPHI = BS + BOFF_WQPHI;
    __nv_bfloat16* WQPLO = BS + BOFF_WQPLO;
    __nv_bfloat16* WA1HI = BS + BOFF_WA1HI;
    __nv_bfloat16* WA1LO = BS + BOFF_WA1LO;
    __nv_bfloat16* WTEHI = BS + BOFF_WTEHI;
    __nv_bfloat16* WTELO = BS + BOFF_WTELO;

    const long long G0_MP = 1024LL * 10;
    const long long G1_MP = 10240LL * 10;
    const long long G2_MP = 1024LL * 10;
    const long long QP_MP = 4096LL * 1024;
    const long long M1_MP = 10240LL * 64;
    const long long R_MP  = 1024LL * 64;
    const long long TE_MP = 10240LL * 64;
    const long long E0_MP = 10240LL * 64;
    const long long H0_MP = 1024LL * 512;
    const long long H1_MP = 10240LL * 512;
    const long long X2_MP = 1024LL * 1024;
    const long long OUT_MP = 1024LL * 512;
    const long long VG_MP = 2LL * 64;

    const long long WQP_SL = 1024LL * 512;    // folded [1024,512] per mp
    const long long WA1_SL = 512LL * 1024;    // [512,1024] per mp
    const long long WTE_SL = 64LL * 1088;     // [64,1088] per mp

    const int SMEM128 = 2 * (2 * 128 * 40 + 2 * 128 * 40) * 2;   // 81920 B
    const int SMEM64  = 2 * (2 * 128 * 40 + 2 * 64 * 40) * 2;    // 61440 B
    const int SMEM_AF = (32 * 512 + 8192) * 4;                   // 98304 B
    cudaFuncSetAttribute(bf16_gemm<128>,
                         cudaFuncAttributeMaxDynamicSharedMemorySize, SMEM128);
    cudaFuncSetAttribute(bf16_gemm<64>,
                         cudaFuncAttributeMaxDynamicSharedMemorySize, SMEM64);
    cudaFuncSetAttribute(att_final_kernel,
                         cudaFuncAttributeMaxDynamicSharedMemorySize, SMEM_AF);

    // 0) weight prep
    //    W_agg[mp][0] -> folded WQP [mp][1024][512]
    transpose_split_kernel<<<dim3(32, 16, 2), dim3(32, 8)>>>(
        W_agg, 2LL * 1024 * 512, WQPHI, WQPLO, WQP_SL, 1024, 512, 1);
    //    W_agg[mp][1] -> WA1 [mp][512][1024]
    transpose_split_kernel<<<dim3(32, 16, 2), dim3(32, 8)>>>(
        W_agg + 1024LL * 512, 2LL * 1024 * 512, WA1HI, WA1LO, WA1_SL, 1024, 512, 0);
    //    W_edge[mp][0] -> WTE [mp][64][1088]
    transpose_split_kernel<<<dim3(34, 2, 2), dim3(32, 8)>>>(
        W_edge, 2LL * 1088 * 64, WTEHI, WTELO, WTE_SL, 1088, 64, 0);
    // feats -> bf16 planes
    split_rows_kernel<<<N_NODES, 128>>>(feats, FHI, FLO);
    // per-edge scores
    edge_score_kernel<<<N_EDGES / 8, 256>>>(edge_emb, v_gate, VG_MP, ES);

    // 1) hop-1 gating + E0 planes
    edge_gate_kernel<<<dim3(N1_ROWS / 4, N_MP), 128>>>(
        ids, n1, (long long)N1_ROWS * S_FAN, adjs, edge_emb,
        v_gate, VG_MP, G0, G0_MP, E0HI, E0LO, E0_MP, N1_ROWS);
    // 2) hop-2 gating via ES
    gate2_kernel<<<dim3(N2_ROWS / 256, N_MP), 256>>>(
        n1, (long long)N1_ROWS * S_FAN, n2, (long long)N2_ROWS * S_FAN,
        adjs, ES, G1, G1_MP);

    // 3) QP = feats @ [Wtop|Wbot]  -> [4096, 1024] per mp
    bf16_gemm<128><<<dim3(8, 32, N_MP), 256, SMEM128>>>(
        FHI, FLO, 0, 512, WQPHI, WQPLO, WQP_SL, 512,
        nullptr, 0, QP, QP_MP, 1024, 512);

    // 4) combines
    combine_kernel<<<dim3(N2_ROWS, N_MP), 128>>>(
        QP, QP_MP, n1, (long long)N1_ROWS * S_FAN,
        n2, (long long)N2_ROWS * S_FAN, G1, G1_MP,
        b_agg, 2LL * 512, H1HI, H1LO, H1_MP);
    combine_kernel<<<dim3(N1_ROWS, N_MP), 128>>>(
        QP, QP_MP, ids, 0,
        n1, (long long)N1_ROWS * S_FAN, G0, G0_MP,
        b_agg, 2LL * 512, H0HI, H0LO, H0_MP);

    // 5) edge-update partial GEMMs
    bf16_gemm<64><<<dim3(1, 80, N_MP), 256, SMEM64>>>(
        H1HI, H1LO, H1_MP, 512, WTEHI + 512, WTELO + 512, WTE_SL, 1088,
        nullptr, 0, M1, M1_MP, 64, 512);
    bf16_gemm<64><<<dim3(1, 8, N_MP), 256, SMEM64>>>(
        H0HI, H0LO, H0_MP, 512, WTEHI, WTELO, WTE_SL, 1088,
        nullptr, 0, R, R_MP, 64, 512);
    bf16_gemm<64><<<dim3(1, 80, N_MP), 256, SMEM64>>>(
        E0HI, E0LO, E0_MP, 64, WTEHI + 1024, WTELO + 1024, WTE_SL, 1088,
        nullptr, 0, TE, TE_MP, 64, 64);

    // 6) layer-1 gate scores
    scores_kernel<<<dim3(N1_ROWS / 4, N_MP), 128>>>(
        R, R_MP, M1, M1_MP, TE, TE_MP, b_edge, 2LL * 64,
        v_gate + E_DIM, VG_MP, G2, G2_MP);

    // 7) X2 = [H0 | sum_s G2*H1]
    build_x2_kernel<<<dim3(N1_ROWS, N_MP), 128>>>(
        H0HI, H0LO, H0_MP, H1HI, H1LO, H1_MP, G2, G2_MP, X2HI, X2LO, X2_MP);

    // 8) OUT = relu(X2 @ W_agg[mp,1] + b_agg[mp,1])
    bf16_gemm<128><<<dim3(4, 8, N_MP), 256, SMEM128>>>(
        X2HI, X2LO, X2_MP, 1024, WA1HI, WA1LO, WA1_SL, 1024,
        b_agg + 512, 2LL * 512, OUTB, OUT_MP, 512, 1024);

    // 9) fused attention + FC
    att_final_kernel<<<B_SZ / 16, 256, SMEM_AF>>>(
        OUTB, Wa, ba, va, W_fc, b_fc, out);
}

// round 7
// speedup vs baseline: 1.0281x; 1.0281x over previous
#include <cuda_runtime.h>
#include <cuda_bf16.h>
#include <math.h>
#include <stdint.h>

// ---------------------------------------------------------------------------
// Problem constants
// ---------------------------------------------------------------------------
#define N_MP 2
#define B_SZ 1024
#define S_FAN 10
#define D_DIM 512
#define E_DIM 64
#define ATT_DIM 128
#define N_CLASSES 8
#define N_NODES 4096
#define N_EDGES 65536

#define N1_ROWS (B_SZ)            // 1024
#define N2_ROWS (B_SZ * S_FAN)    // 10240
#define HE1_LD  (D_DIM + E_DIM)   // 576: H1 planes row = [H1(512) | E0(64)]

// ---------------------------------------------------------------------------
// fp32 scratch arena
// ---------------------------------------------------------------------------
#define OFF_G0   0LL
#define SZ_G0    (2LL*1024*10)
#define OFF_G1   (OFF_G0 + SZ_G0)
#define SZ_G1    (2LL*10240*10)
#define OFF_G2   (OFF_G1 + SZ_G1)
#define SZ_G2    (2LL*1024*10)
#define OFF_QP   (OFF_G2 + SZ_G2)
#define SZ_QP    (2LL*4096*1024)
#define OFF_SCR  (OFF_QP + SZ_QP)
#define SZ_SCR   (2LL*10240*64)
#define OFF_R    (OFF_SCR + SZ_SCR)
#define SZ_R     (2LL*1024*64)
#define OFF_OUT  (OFF_R + SZ_R)
#define SZ_OUT   (2LL*1024*512)
#define OFF_ES   (OFF_OUT + SZ_OUT)
#define SZ_ES    (2LL*N_EDGES)
#define FARENA_TOTAL (OFF_ES + SZ_ES)

__device__ float g_scratch[FARENA_TOTAL];

// ---------------------------------------------------------------------------
// bf16 scratch arena (hi/lo operand planes)
// ---------------------------------------------------------------------------
#define BOFF_FHI    0LL
#define BSZ_F       (4096LL*512)
#define BOFF_FLO    (BOFF_FHI + BSZ_F)
#define BOFF_HE1HI  (BOFF_FLO + BSZ_F)
#define BSZ_HE1     (2LL*10240*HE1_LD)
#define BOFF_HE1LO  (BOFF_HE1HI + BSZ_HE1)
#define BOFF_H0HI   (BOFF_HE1LO + BSZ_HE1)
#define BSZ_H0      (2LL*1024*512)
#define BOFF_H0LO   (BOFF_H0HI + BSZ_H0)
#define BOFF_X2HI   (BOFF_H0LO + BSZ_H0)
#define BSZ_X2      (2LL*1024*1024)
#define BOFF_X2LO   (BOFF_X2HI + BSZ_X2)
#define BOFF_WQPHI  (BOFF_X2LO + BSZ_X2)
#define BSZ_WQP     (2LL*1024*512)
#define BOFF_WQPLO  (BOFF_WQPHI + BSZ_WQP)
#define BOFF_WA1HI  (BOFF_WQPLO + BSZ_WQP)
#define BSZ_WA1     (2LL*512*1024)
#define BOFF_WA1LO  (BOFF_WA1HI + BSZ_WA1)
#define BOFF_WTEHI  (BOFF_WA1LO + BSZ_WA1)
#define BSZ_WTE     (2LL*64*1088)
#define BOFF_WTELO  (BOFF_WTEHI + BSZ_WTE)
#define BARENA_TOTAL (BOFF_WTELO + BSZ_WTE)

__device__ __nv_bfloat16 g_bscratch[BARENA_TOTAL];

// ---------------------------------------------------------------------------
// helpers
// ---------------------------------------------------------------------------
__device__ __forceinline__ uint32_t smem_u32(const void* p) {
    uint32_t a;
    asm("{ .reg .u64 t; cvta.to.shared.u64 t, %1; cvt.u32.u64 %0, t; }"
        : "=r"(a) : "l"(p));
    return a;
}

#define CP_ASYNC16(dst, src) \
    asm volatile("cp.async.cg.shared.global [%0], [%1], 16;" :: "r"(dst), "l"(src))
#define CP_COMMIT() asm volatile("cp.async.commit_group;")
#define CP_WAIT(n)  asm volatile("cp.async.wait_group %0;" :: "n"(n))

#define LDSM4(r, addr) \
    asm volatile("ldmatrix.sync.aligned.m8n8.x4.shared.b16 {%0,%1,%2,%3}, [%4];" \
        : "=r"((r)[0]), "=r"((r)[1]), "=r"((r)[2]), "=r"((r)[3]) : "r"(addr))
#define LDSM2(r, addr) \
    asm volatile("ldmatrix.sync.aligned.m8n8.x2.shared.b16 {%0,%1}, [%2];" \
        : "=r"((r)[0]), "=r"((r)[1]) : "r"(addr))

#define MMA_BF16(d, a, b) \
    asm volatile( \
        "mma.sync.aligned.m16n8k16.row.col.f32.bf16.bf16.f32 " \
        "{%0,%1,%2,%3}, {%4,%5,%6,%7}, {%8,%9}, {%0,%1,%2,%3};" \
        : "+f"((d)[0]), "+f"((d)[1]), "+f"((d)[2]), "+f"((d)[3]) \
        : "r"((a)[0]), "r"((a)[1]), "r"((a)[2]), "r"((a)[3]), \
          "r"((b)[0]), "r"((b)[1]))

__device__ __forceinline__ uint32_t pack2(float a, float b) {
    __nv_bfloat162 h = __floats2bfloat162_rn(a, b);
    return *(uint32_t*)&h;
}

__device__ __forceinline__ void store_split4(
    __nv_bfloat16* Ohi, __nv_bfloat16* Olo, long long base, const float* a)
{
    float h[4], l[4];
#pragma unroll
    for (int i = 0; i < 4; i++) {
        h[i] = __bfloat162float(__float2bfloat16_rn(a[i]));
        l[i] = a[i] - h[i];
    }
    *(uint32_t*)(Ohi + base)     = pack2(h[0], h[1]);
    *(uint32_t*)(Ohi + base + 2) = pack2(h[2], h[3]);
    *(uint32_t*)(Olo + base)     = pack2(l[0], l[1]);
    *(uint32_t*)(Olo + base + 2) = pack2(l[2], l[3]);
}

// ---------------------------------------------------------------------------
// Uber weight transpose + bf16 hi/lo split. z = cfg*2 + mp.
// cfg 0: W_agg[mp][0] K=1024,N=512, fold -> WQP [1024][512]
// cfg 1: W_agg[mp][1] K=1024,N=512        -> WA1 [512][1024]
// cfg 2: W_edge[mp][0] K=1088,N=64        -> WTE [64][1088]
// ---------------------------------------------------------------------------
__global__ void transpose_uber_kernel(
    const float* __restrict__ W_agg, const float* __restrict__ W_edge,
    __nv_bfloat16* __restrict__ WQPHI, __nv_bfloat16* __restrict__ WQPLO,
    __nv_bfloat16* __restrict__ WA1HI, __nv_bfloat16* __restrict__ WA1LO,
    __nv_bfloat16* __restrict__ WTEHI, __nv_bfloat16* __restrict__ WTELO)
{
    __shared__ float t[32][33];
    int z = blockIdx.z, mp = z & 1, cfg = z >> 1;
    const float* Wp;
    __nv_bfloat16 *ho, *lo;
    int K, N, fold;
    if (cfg == 0) {
        Wp = W_agg + (long long)mp * 2 * 1024 * 512;
        K = 1024; N = 512; fold = 1;
        ho = WQPHI + (long long)mp * 1024 * 512;
        lo = WQPLO + (long long)mp * 1024 * 512;
    } else if (cfg == 1) {
        Wp = W_agg + 1024LL * 512 + (long long)mp * 2 * 1024 * 512;
        K = 1024; N = 512; fold = 0;
        ho = WA1HI + (long long)mp * 512 * 1024;
        lo = WA1LO + (long long)mp * 512 * 1024;
    } else {
        Wp = W_edge + (long long)mp * 2 * 1088 * 64;
        K = 1088; N = 64; fold = 0;
        ho = WTEHI + (long long)mp * 64 * 1088;
        lo = WTELO + (long long)mp * 64 * 1088;
    }
    int k0 = blockIdx.x * 32, n0 = blockIdx.y * 32;
    if (k0 >= K || n0 >= N) return;
    for (int r = threadIdx.y; r < 32; r += 8)
        t[r][threadIdx.x] = Wp[(long long)(k0 + r) * N + n0 + threadIdx.x];
    __syncthreads();
    int khalf = K >> 1;
    for (int r = threadIdx.y; r < 32; r += 8) {
        float v = t[threadIdx.x][r];          // W[k0+tx][n0+r]
        int k = k0 + threadIdx.x, n = n0 + r;
        long long o;
        if (fold) {
            int hi = (k >= khalf) ? 1 : 0;
            o = (long long)(n + hi * N) * khalf + (k - hi * khalf);
        } else {
            o = (long long)n * K + k;
        }
        float h = __bfloat162float(__float2bfloat16_rn(v));
        ho[o] = __float2bfloat16_rn(h);
        lo[o] = __float2bfloat16_rn(v - h);
    }
}

// ---------------------------------------------------------------------------
// feats rows -> bf16 hi/lo planes (512 cols)
// ---------------------------------------------------------------------------
__global__ void split_rows_kernel(
    const float* __restrict__ src,
    __nv_bfloat16* __restrict__ Ohi, __nv_bfloat16* __restrict__ Olo)
{
    int row = blockIdx.x, t = threadIdx.x;
    float4 v = ((const float4*)(src + (long long)row * D_DIM))[t];
    float a[4] = {v.x, v.y, v.z, v.w};
    store_split4(Ohi, Olo, (long long)row * D_DIM + t * 4, a);
}

// ---------------------------------------------------------------------------
// Per-edge gate scores ES[mp][e] = edge_emb[e] · v_gate[mp,0]
// ---------------------------------------------------------------------------
__global__ void edge_score_kernel(
    const float* __restrict__ edge_emb,
    const float* __restrict__ vg, long long vg_mp,
    float* __restrict__ ES)
{
    int e = blockIdx.x * 8 + (threadIdx.x >> 5);
    int lane = threadIdx.x & 31;
    const float* er = edge_emb + (long long)e * E_DIM;
    float e0 = er[lane], e1 = er[lane + 32];
#pragma unroll
    for (int mp = 0; mp < N_MP; mp++) {
        const float* vgp = vg + (long long)mp * vg_mp;
        float p = e0 * vgp[lane] + e1 * vgp[lane + 32];
#pragma unroll
        for (int off = 16; off; off >>= 1)
            p += __shfl_xor_sync(0xffffffffu, p, off);
        if (lane == 0) ES[(long long)mp * N_EDGES + e] = p;
    }
}

// ---------------------------------------------------------------------------
// Hop-2 gating via precomputed ES: one thread per row.
// ---------------------------------------------------------------------------
__global__ void gate2_kernel(
    const int* __restrict__ n1, long long n1_mp,
    const int* __restrict__ n2, long long n2_mp,
    const int* __restrict__ adjs,
    const float* __restrict__ ES,
    float* __restrict__ G1, long long g_mp)
{
    int mp = blockIdx.y;
    int r = blockIdx.x * 256 + threadIdx.x;
    if (r >= N2_ROWS) return;
    int src = n1[(long long)mp * n1_mp + r];
    const int* nbp = n2 + (long long)mp * n2_mp + (long long)r * S_FAN;
    const float* esp = ES + (long long)mp * N_EDGES;
    const int* arow = adjs + (long long)src * N_NODES;
    float sc[S_FAN];
#pragma unroll
    for (int s = 0; s < S_FAN; s++)
        sc[s] = esp[arow[nbp[s]]];
    float m = sc[0];
#pragma unroll
    for (int s = 1; s < S_FAN; s++) m = fmaxf(m, sc[s]);
    float sum = 0.f;
#pragma unroll
    for (int s = 0; s < S_FAN; s++) { sc[s] = expf(sc[s] - m); sum += sc[s]; }
    float inv = 1.f / sum;
    float* go = G1 + (long long)mp * g_mp + (long long)r * S_FAN;
#pragma unroll
    for (int s = 0; s < S_FAN; s++) go[s] = sc[s] * inv;
}

// ---------------------------------------------------------------------------
// Hop-1 gating: one warp per row; also stores E0 rows into cols [512,576) of
// the HE1 plane rows (stride HE1_LD).
// ---------------------------------------------------------------------------
__global__ void edge_gate_kernel(
    const int* __restrict__ src_ids,
    const int* __restrict__ nb_ids,  long long nb_mp,
    const int* __restrict__ adjs,
    const float* __restrict__ edge_emb,
    const float* __restrict__ vg, long long vg_mp,
    float* __restrict__ gate_out, long long gate_mp,
    __nv_bfloat16* __restrict__ he_hi, __nv_bfloat16* __restrict__ he_lo,
    long long he_mp, int n_rows)
{
    int mp   = blockIdx.y;
    int warp = threadIdx.x >> 5;
    int lane = threadIdx.x & 31;
    int row  = blockIdx.x * (blockDim.x >> 5) + warp;
    if (row >= n_rows) return;

    const float* vgp = vg + (long long)mp * vg_mp;
    float v0 = vgp[lane], v1 = vgp[lane + 32];
    int srcn = src_ids[row];

    float scores[S_FAN];
#pragma unroll
    for (int s = 0; s < S_FAN; s++) {
        int nb = nb_ids[(long long)mp * nb_mp + (long long)row * S_FAN + s];
        int eid = adjs[(long long)srcn * N_NODES + nb];
        const float* er = edge_emb + (long long)eid * E_DIM;
        float e0 = er[lane], e1 = er[lane + 32];
        long long eo = (long long)mp * he_mp +
                       ((long long)row * S_FAN + s) * HE1_LD + D_DIM;
        __nv_bfloat16 h0 = __float2bfloat16_rn(e0);
        __nv_bfloat16 h1 = __float2bfloat16_rn(e1);
        he_hi[eo + lane]      = h0;
        he_hi[eo + lane + 32] = h1;
        he_lo[eo + lane]      = __float2bfloat16_rn(e0 - __bfloat162float(h0));
        he_lo[eo + lane + 32] = __float2bfloat16_rn(e1 - __bfloat162float(h1));
        float p = e0 * v0 + e1 * v1;
#pragma unroll
        for (int off = 16; off; off >>= 1)
            p += __shfl_xor_sync(0xffffffffu, p, off);
        scores[s] = p;
    }
    float m = scores[0];
#pragma unroll
    for (int s = 1; s < S_FAN; s++) m = fmaxf(m, scores[s]);
    float sum = 0.f;
#pragma unroll
    for (int s = 0; s < S_FAN; s++) { scores[s] = expf(scores[s] - m); sum += scores[s]; }
    float inv = 1.f / sum;
    float* go = gate_out + (long long)mp * gate_mp + (long long)row * S_FAN;
#pragma unroll
    for (int s = 0; s < S_FAN; s++)
        if (lane == s) go[s] = scores[s] * inv;
}

// ---------------------------------------------------------------------------
// General bf16 3-pass GEMM. C = [relu](A@B^T [+ bias])
// BM=128, BK=32, 256 threads, double buffered cp.async.
// ---------------------------------------------------------------------------
template<int BN>
__global__ __launch_bounds__(256)
void bf16_gemm(
    const __nv_bfloat16* __restrict__ Ahi, const __nv_bfloat16* __restrict__ Alo,
    long long A_mp, int lda,
    const __nv_bfloat16* __restrict__ Bhi, const __nv_bfloat16* __restrict__ Blo,
    long long B_mp, int ldb,
    const float* __restrict__ bias, long long bias_mp,
    float* __restrict__ C, long long C_mp, int ldc,
    int K)
{
    constexpr int BM = 128, BK = 32;
    constexpr int LDS = 40;
    constexpr int A_MAT = BM * LDS;
    constexpr int B_MAT = BN * LDS;
    constexpr int STAGE = 2 * A_MAT + 2 * B_MAT;
    constexpr int MT = 4;
    constexpr int NT = BN / 32;
    constexpr uint32_t OFF_ALO = A_MAT * 2;
    constexpr uint32_t OFF_BHI = 2 * A_MAT * 2;

    extern __shared__ __nv_bfloat16 smem[];
    uint32_t sbase0 = smem_u32(smem);

    int tid  = threadIdx.x;
    int wid  = tid >> 5;
    int lane = tid & 31;
    int wm   = wid >> 2;
    int wn   = wid & 3;
    int mp   = blockIdx.z;

    const __nv_bfloat16* Ahp = Ahi + (long long)mp * A_mp + (long long)blockIdx.y * BM * lda;
    const __nv_bfloat16* Alp = Alo + (long long)mp * A_mp + (long long)blockIdx.y * BM * lda;
    const __nv_bfloat16* Bhp = Bhi + (long long)mp * B_mp + (long long)blockIdx.x * BN * ldb;
    const __nv_bfloat16* Blp = Blo + (long long)mp * B_mp + (long long)blockIdx.x * BN * ldb;

    const int NKB = K / BK;

    auto issue = [&](int kb, int s) {
        int k0 = kb * BK;
        uint32_t sb = sbase0 + (uint32_t)s * STAGE * 2u;
#pragma unroll
        for (int i = 0; i < (BM * 4) / 256; i++) {
            int c = tid + i * 256;
            int row = c >> 2, ch = c & 3;
            long long g = (long long)row * lda + k0 + ch * 8;
            uint32_t d = sb + (uint32_t)(row * 80 + ch * 16);
            CP_ASYNC16(d, Ahp + g);
            CP_ASYNC16(d + OFF_ALO, Alp + g);
        }
#pragma unroll
        for (int i = 0; i < (BN * 4) / 256; i++) {
            int c = tid + i * 256;
            int row = c >> 2, ch = c & 3;
            long long g = (long long)row * ldb + k0 + ch * 8;
            uint32_t d = sb + OFF_BHI + (uint32_t)(row * 80 + ch * 16);
            CP_ASYNC16(d, Bhp + g);
            CP_ASYNC16(d + (uint32_t)(B_MAT * 2), Blp + g);
        }
        CP_COMMIT();
    };

    float acc[MT][NT][4];
#pragma unroll
    for (int i = 0; i < MT; i++)
#pragma unroll
        for (int j = 0; j < NT; j++)
#pragma unroll
            for (int q = 0; q < 4; q++) acc[i][j][q] = 0.f;

    issue(0, 0);

    for (int kb = 0; kb < NKB; kb++) {
        int s = kb & 1;
        if (kb + 1 < NKB) { issue(kb + 1, s ^ 1); CP_WAIT(1); }
        else              { CP_WAIT(0); }
        __syncthreads();

        uint32_t sA = sbase0 + (uint32_t)s * STAGE * 2u;
#pragma unroll
        for (int ks = 0; ks < 2; ks++) {
            uint32_t a_hi[MT][4], a_lo[MT][4];
#pragma unroll
            for (int mi = 0; mi < MT; mi++) {
                int r = wm * 64 + mi * 16 + (lane & 15);
                uint32_t ad = sA + (uint32_t)(r * 80 + ks * 32 + ((lane >> 4) << 4));
                LDSM4(a_hi[mi], ad);
                LDSM4(a_lo[mi], ad + OFF_ALO);
            }
            uint32_t b_hi[NT][2], b_lo[NT][2];
#pragma unroll
            for (int ni = 0; ni < NT; ni++) {
                int r = wn * (BN / 4) + ni * 8 + (lane & 7);
                uint32_t bd = sA + OFF_BHI +
                              (uint32_t)(r * 80 + ks * 32 + (((lane >> 3) & 1) << 4));
                LDSM2(b_hi[ni], bd);
                LDSM2(b_lo[ni], bd + (uint32_t)(B_MAT * 2));
            }
#pragma unroll
            for (int mi = 0; mi < MT; mi++)
#pragma unroll
                for (int ni = 0; ni < NT; ni++) {
                    MMA_BF16(acc[mi][ni], a_hi[mi], b_hi[ni]);
                    MMA_BF16(acc[mi][ni], a_hi[mi], b_lo[ni]);
                    MMA_BF16(acc[mi][ni], a_lo[mi], b_hi[ni]);
                }
        }
        __syncthreads();
    }

    float* Cp = C + (long long)mp * C_mp;
    const float* bp = bias ? bias + (long long)mp * bias_mp : nullptr;
    int mrow0 = blockIdx.y * BM + wm * 64;
#pragma unroll
    for (int mi = 0; mi < MT; mi++) {
#pragma unroll
        for (int ni = 0; ni < NT; ni++) {
            int col = blockIdx.x * BN + wn * (BN / 4) + ni * 8 + (lane & 3) * 2;
            int r0 = mrow0 + mi * 16 + (lane >> 2);
            float v0 = acc[mi][ni][0], v1 = acc[mi][ni][1];
            float v2 = acc[mi][ni][2], v3 = acc[mi][ni][3];
            if (bp) {
                float b0 = __ldg(bp + col), b1 = __ldg(bp + col + 1);
                v0 = fmaxf(v0 + b0, 0.f); v1 = fmaxf(v1 + b1, 0.f);
                v2 = fmaxf(v2 + b0, 0.f); v3 = fmaxf(v3 + b1, 0.f);
            }
            Cp[(long long)r0 * ldc + col]           = v0;
            Cp[(long long)r0 * ldc + col + 1]       = v1;
            Cp[(long long)(r0 + 8) * ldc + col]     = v2;
            Cp[(long long)(r0 + 8) * ldc + col + 1] = v3;
        }
    }
}

// ---------------------------------------------------------------------------
// Merged combine: grid.x = N2_ROWS + N1_ROWS.
// rows [0, 10240):   H1[r] = relu(Q[n1[r]] + sum_s G1*P[n2[r,s]] + b)
//                    -> HE1 planes (stride 576, cols [0,512))
// rows [10240, 11264): H0[r'] = relu(Q[ids[r']] + sum_s G0*P[n1[r',s]] + b)
//                    -> H0 planes (stride 512)
// ---------------------------------------------------------------------------
__global__ void combine_kernel(
    const float* __restrict__ QP, long long qp_mp,
    const int* __restrict__ ids,
    const int* __restrict__ n1, long long n1_mp,
    const int* __restrict__ n2, long long n2_mp,
    const float* __restrict__ G0, long long g0_mp,
    const float* __restrict__ G1, long long g1_mp,
    const float* __restrict__ bias, long long bias_mp,
    __nv_bfloat16* __restrict__ HE1hi, __nv_bfloat16* __restrict__ HE1lo,
    long long he_mp,
    __nv_bfloat16* __restrict__ H0hi, __nv_bfloat16* __restrict__ H0lo,
    long long h0_mp)
{
    int mp = blockIdx.y, row = blockIdx.x, t = threadIdx.x;
    const float* Qp = QP + (long long)mp * qp_mp;
    const float* Pp = Qp + D_DIM;

    int sid;
    const int* nbp;
    const float* gp;
    __nv_bfloat16 *Ohi, *Olo;
    long long obase;
    if (row < N2_ROWS) {
        sid = n1[(long long)mp * n1_mp + row];
        nbp = n2 + (long long)mp * n2_mp + (long long)row * S_FAN;
        gp  = G1 + (long long)mp * g1_mp + (long long)row * S_FAN;
        Ohi = HE1hi; Olo = HE1lo;
        obase = (long long)mp * he_mp + (long long)row * HE1_LD + t * 4;
    } else {
        int r2 = row - N2_ROWS;
        sid = ids[r2];
        nbp = n1 + (long long)mp * n1_mp + (long long)r2 * S_FAN;
        gp  = G0 + (long long)mp * g0_mp + (long long)r2 * S_FAN;
        Ohi = H0hi; Olo = H0lo;
        obase = (long long)mp * h0_mp + (long long)r2 * D_DIM + t * 4;
    }

    float4 q = ((const float4*)(Qp + (long long)sid * 1024))[t];
    float a[4] = {q.x, q.y, q.z, q.w};
#pragma unroll
    for (int s = 0; s < S_FAN; s++) {
        float w = gp[s];
        int idx = nbp[s];
        float4 v = ((const float4*)(Pp + (long long)idx * 1024))[t];
        a[0] = fmaf(w, v.x, a[0]);
        a[1] = fmaf(w, v.y, a[1]);
        a[2] = fmaf(w, v.z, a[2]);
        a[3] = fmaf(w, v.w, a[3]);
    }
    float4 b = ((const float4*)(bias + (long long)mp * bias_mp))[t];
    a[0] = fmaxf(a[0] + b.x, 0.f);
    a[1] = fmaxf(a[1] + b.y, 0.f);
    a[2] = fmaxf(a[2] + b.z, 0.f);
    a[3] = fmaxf(a[3] + b.w, 0.f);
    store_split4(Ohi, Olo, obase, a);
}

// ---------------------------------------------------------------------------
// Layer-1 gate scores: NE[i] = relu(R[i/10] + SCR[i] + b_edge); dot v_gate;
// softmax over S. One warp per output row.
// ---------------------------------------------------------------------------
__global__ void scores_kernel(
    const float* __restrict__ R, long long r_mp,
    const float* __restrict__ SCR, long long scr_mp,
    const float* __restrict__ be, long long be_mp,
    const float* __restrict__ vg, long long vg_mp,
    float* __restrict__ G2, long long g_mp)
{
    int mp = blockIdx.y;
    int warp = threadIdx.x >> 5, lane = threadIdx.x & 31;
    int r = blockIdx.x * 4 + warp;

    const float* vgp = vg + (long long)mp * vg_mp;
    float v0 = vgp[lane], v1 = vgp[lane + 32];
    float b0 = be[(long long)mp * be_mp + lane];
    float b1 = be[(long long)mp * be_mp + lane + 32];
    float r0 = R[(long long)mp * r_mp + (long long)r * E_DIM + lane];
    float r1 = R[(long long)mp * r_mp + (long long)r * E_DIM + lane + 32];

    float sc[S_FAN];
#pragma unroll
    for (int s = 0; s < S_FAN; s++) {
        long long i = (long long)r * S_FAN + s;
        float a0 = r0 + SCR[(long long)mp * scr_mp + i * E_DIM + lane] + b0;
        float a1 = r1 + SCR[(long long)mp * scr_mp + i * E_DIM + lane + 32] + b1;
        float p = fmaxf(a0, 0.f) * v0 + fmaxf(a1, 0.f) * v1;
#pragma unroll
        for (int off = 16; off; off >>= 1)
            p += __shfl_xor_sync(0xffffffffu, p, off);
        sc[s] = p;
    }
    float m = sc[0];
#pragma unroll
    for (int s = 1; s < S_FAN; s++) m = fmaxf(m, sc[s]);
    float sum = 0.f;
#pragma unroll
    for (int s = 0; s < S_FAN; s++) { sc[s] = expf(sc[s] - m); sum += sc[s]; }
    float inv = 1.f / sum;
    float* go = G2 + (long long)mp * g_mp + (long long)r * S_FAN;
#pragma unroll
    for (int s = 0; s < S_FAN; s++)
        if (lane == s) go[s] = sc[s] * inv;
}

// ---------------------------------------------------------------------------
// Build X2 planes: [H0 | gate-weighted sum of H1 (from HE1, stride 576)]
// ---------------------------------------------------------------------------
__global__ void build_x2_kernel(
    const __nv_bfloat16* __restrict__ H0hi, const __nv_bfloat16* __restrict__ H0lo,
    long long h0_mp,
    const __nv_bfloat16* __restrict__ HE1hi, const __nv_bfloat16* __restrict__ HE1lo,
    long long he_mp,
    const float* __restrict__ G2, long long g_mp,
    __nv_bfloat16* __restrict__ Xhi, __nv_bfloat16* __restrict__ Xlo,
    long long x_mp)
{
    int mp = blockIdx.y, r = blockIdx.x, t = threadIdx.x;
    long long hb = (long long)mp * h0_mp + (long long)r * D_DIM + t * 4;
    long long xb = (long long)mp * x_mp + (long long)r * (2 * D_DIM) + t * 4;
    *(uint2*)(Xhi + xb) = *(const uint2*)(H0hi + hb);
    *(uint2*)(Xlo + xb) = *(const uint2*)(H0lo + hb);

    const float* gp = G2 + (long long)mp * g_mp + (long long)r * S_FAN;
    float a[4] = {0.f, 0.f, 0.f, 0.f};
#pragma unroll
    for (int s = 0; s < S_FAN; s++) {
        float w = gp[s];
        long long p = (long long)mp * he_mp + ((long long)r * S_FAN + s) * HE1_LD + t * 4;
        uint2 uh = *(const uint2*)(HE1hi + p);
        uint2 ul = *(const uint2*)(HE1lo + p);
        float2 h0 = __bfloat1622float2(*(__nv_bfloat162*)&uh.x);
        float2 h1 = __bfloat1622float2(*(__nv_bfloat162*)&uh.y);
        float2 l0 = __bfloat1622float2(*(__nv_bfloat162*)&ul.x);
        float2 l1 = __bfloat1622float2(*(__nv_bfloat162*)&ul.y);
        a[0] = fmaf(w, h0.x + l0.x, a[0]);
        a[1] = fmaf(w, h0.y + l0.y, a[1]);
        a[2] = fmaf(w, h1.x + l1.x, a[2]);
        a[3] = fmaf(w, h1.y + l1.y, a[3]);
    }
    store_split4(Xhi, Xlo, xb + D_DIM, a);
}

// ---------------------------------------------------------------------------
// Fused metapath attention + softmax + FC. Block = 16 batch items.
// ---------------------------------------------------------------------------
__global__ __launch_bounds__(256)
void att_final_kernel(
    const float* __restrict__ OUTB,
    const float* __restrict__ Wa, const float* __restrict__ ba,
    const float* __restrict__ va,
    const float* __restrict__ W_fc, const float* __restrict__ b_fc,
    float* __restrict__ out)
{
    extern __shared__ float sm[];
    float* srow = sm;               // 32 x 512
    float* swa  = sm + 32 * 512;    // 8192 floats
    __shared__ float s_att[32];

    int tid = threadIdx.x;
    int j = tid & 127, g = tid >> 7;
    int b0 = blockIdx.x * 16;

    for (int i = tid; i < 32 * 128; i += 256) {
        int r = i >> 7, c = i & 127;
        int mp = r >> 4, bi = r & 15;
        ((float4*)srow)[r * 128 + c] =
            ((const float4*)(OUTB + ((long long)mp * B_SZ + b0 + bi) * D_DIM))[c];
    }

    float acc[16];
#pragma unroll
    for (int i = 0; i < 16; i++) acc[i] = 0.f;

    for (int kt = 0; kt < 8; kt++) {
        __syncthreads();
        for (int i = tid; i < 64 * 32; i += 256)
            ((float4*)swa)[i] = ((const float4*)(Wa + (long long)kt * 64 * ATT_DIM))[i];
        __syncthreads();
#pragma unroll 4
        for (int k = 0; k < 64; k++) {
            float w = swa[k * 128 + j];
            int kk = kt * 64 + k;
#pragma unroll
            for (int i = 0; i < 16; i++)
                acc[i] = fmaf(srow[(g * 16 + i) * 512 + kk], w, acc[i]);
        }
    }
    __syncthreads();
    float baj = ba[j], vaj = va[j];
#pragma unroll
    for (int i = 0; i < 16; i++)
        swa[(g * 16 + i) * 128 + j] = tanhf(acc[i] + baj) * vaj;
    __syncthreads();
    int wid = tid >> 5, lane = tid & 31;
#pragma unroll
    for (int q = 0; q < 4; q++) {
        int r = wid * 4 + q;
        float s = swa[r * 128 + lane] + swa[r * 128 + lane + 32]
                + swa[r * 128 + lane + 64] + swa[r * 128 + lane + 96];
#pragma unroll
        for (int off = 16; off; off >>= 1)
            s += __shfl_xor_sync(0xffffffffu, s, off);
        if (lane == 0) s_att[r] = s;
    }
    __syncthreads();
    for (int i = tid; i < 16 * 128; i += 256) {
        int bi = i >> 7, c = i & 127;
        float a0 = s_att[bi], a1 = s_att[16 + bi];
        float m = fmaxf(a0, a1);
        float e0 = expf(a0 - m), e1 = expf(a1 - m);
        float inv = 1.f / (e0 + e1);
        float w0 = e0 * inv, w1 = e1 * inv;
        float4 v0 = ((float4*)srow)[bi * 128 + c];
        float4 v1 = ((float4*)srow)[(16 + bi) * 128 + c];
        float4 rr;
        rr.x = w0 * v0.x + w1 * v1.x;
        rr.y = w0 * v0.y + w1 * v1.y;
        rr.z = w0 * v0.z + w1 * v1.z;
        rr.w = w0 * v0.w + w1 * v1.w;
        ((float4*)swa)[i] = rr;
    }
    __syncthreads();
    if (tid < 128) {
        int bi = tid >> 3, c = tid & 7;
        float s = 0.f;
#pragma unroll 8
        for (int k = 0; k < D_DIM; k++)
            s = fmaf(swa[bi * 512 + k], __ldg(W_fc + k * N_CLASSES + c), s);
        out[(b0 + bi) * N_CLASSES + c] = fmaxf(s + b_fc[c], 0.f);
    }
}

// ---------------------------------------------------------------------------
// Launch
// ---------------------------------------------------------------------------
extern "C" void kernel_launch(void* const* d_in, const int* in_sizes, int n_in,
                              void* d_out, int out_size)
{
    const int*   ids      = (const int*)d_in[0];
    const float* feats    = (const float*)d_in[1];
    const int*   adjs     = (const int*)d_in[2];
    const float* edge_emb = (const float*)d_in[3];
    const int*   n1       = (const int*)d_in[4];
    const int*   n2       = (const int*)d_in[5];
    const float* W_agg    = (const float*)d_in[6];
    const float* b_agg    = (const float*)d_in[7];
    const float* v_gate   = (const float*)d_in[8];
    const float* W_edge   = (const float*)d_in[9];
    const float* b_edge   = (const float*)d_in[10];
    const float* Wa       = (const float*)d_in[11];
    const float* ba       = (const float*)d_in[12];
    const float* va       = (const float*)d_in[13];
    const float* W_fc     = (const float*)d_in[14];
    const float* b_fc     = (const float*)d_in[15];
    float* out = (float*)d_out;

    float* S;
    cudaGetSymbolAddress((void**)&S, g_scratch);
    __nv_bfloat16* BS;
    cudaGetSymbolAddress((void**)&BS, g_bscratch);

    float* G0   = S + OFF_G0;
    float* G1   = S + OFF_G1;
    float* G2   = S + OFF_G2;
    float* QP   = S + OFF_QP;
    float* SCR  = S + OFF_SCR;
    float* R    = S + OFF_R;
    float* OUTB = S + OFF_OUT;
    float* ES   = S + OFF_ES;

    __nv_bfloat16* FHI   = BS + BOFF_FHI;
    __nv_bfloat16* FLO   = BS + BOFF_FLO;
    __nv_bfloat16* HE1HI = BS + BOFF_HE1HI;
    __nv_bfloat16* HE1LO = BS + BOFF_HE1LO;
    __nv_bfloat16* H0HI  = BS + BOFF_H0HI;
    __nv_bfloat16* H0LO  = BS + BOFF_H0LO;
    __nv_bfloat16* X2HI  = BS + BOFF_X2HI;
    __nv_bfloat16* X2LO  = BS + BOFF_X2LO;
    __nv_bfloat16* WQPHI = BS + BOFF_WQPHI;
    __nv_bfloat16* WQPLO = BS + BOFF_WQPLO;
    __nv_bfloat16* WA1HI = BS + BOFF_WA1HI;
    __nv_bfloat16* WA1LO = BS + BOFF_WA1LO;
    __nv_bfloat16* WTEHI = BS + BOFF_WTEHI;
    __nv_bfloat16* WTELO = BS + BOFF_WTELO;

    const long long G0_MP = 1024LL * 10;
    const long long G1_MP = 10240LL * 10;
    const long long G2_MP = 1024LL * 10;
    const long long QP_MP = 4096LL * 1024;
    const long long SCR_MP = 10240LL * 64;
    const long long R_MP  = 1024LL * 64;
    const long long HE1_MP = 10240LL * HE1_LD;
    const long long H0_MP = 1024LL * 512;
    const long long X2_MP = 1024LL * 1024;
    const long long OUT_MP = 1024LL * 512;
    const long long VG_MP = 2LL * 64;
    const long long WQP_SL = 1024LL * 512;
    const long long WA1_SL = 512LL * 1024;
    const long long WTE_SL = 64LL * 1088;

    const int SMEM128 = 2 * (2 * 128 * 40 + 2 * 128 * 40) * 2;   // 81920 B
    const int SMEM64  = 2 * (2 * 128 * 40 + 2 * 64 * 40) * 2;    // 61440 B
    const int SMEM_AF = (32 * 512 + 8192) * 4;                   // 98304 B
    cudaFuncSetAttribute(bf16_gemm<128>,
                         cudaFuncAttributeMaxDynamicSharedMemorySize, SMEM128);
    cudaFuncSetAttribute(bf16_gemm<64>,
                         cudaFuncAttributeMaxDynamicSharedMemorySize, SMEM64);
    cudaFuncSetAttribute(att_final_kernel,
                         cudaFuncAttributeMaxDynamicSharedMemorySize, SMEM_AF);

    // --- prep (launches 1-5; all independent of the big GEMM) ---
    transpose_uber_kernel<<<dim3(34, 16, 6), dim3(32, 8)>>>(
        W_agg, W_edge, WQPHI, WQPLO, WA1HI, WA1LO, WTEHI, WTELO);
    split_rows_kernel<<<N_NODES, 128>>>(feats, FHI, FLO);
    edge_score_kernel<<<N_EDGES / 8, 256>>>(edge_emb, v_gate, VG_MP, ES);
    gate2_kernel<<<dim3(N2_ROWS / 256, N_MP), 256>>>(
        n1, (long long)N2_ROWS, n2, (long long)N2_ROWS * S_FAN,
        adjs, ES, G1, G1_MP);
    edge_gate_kernel<<<dim3(N1_ROWS / 4, N_MP), 128>>>(
        ids, n1, (long long)N2_ROWS, adjs, edge_emb,
        v_gate, VG_MP, G0, G0_MP, HE1HI, HE1LO, HE1_MP, N1_ROWS);

    // --- launch 6: the big QP GEMM (profiled by ncu -s 5 -c 1) ---
    bf16_gemm<128><<<dim3(8, 32, N_MP), 256, SMEM128>>>(
        FHI, FLO, 0, 512, WQPHI, WQPLO, WQP_SL, 512,
        nullptr, 0, QP, QP_MP, 1024, 512);

    // 7) merged combine (H1 rows then H0 rows)
    combine_kernel<<<dim3(N2_ROWS + N1_ROWS, N_MP), 128>>>(
        QP, QP_MP, ids, n1, (long long)N2_ROWS,
        n2, (long long)N2_ROWS * S_FAN,
        G0, G0_MP, G1, G1_MP, b_agg, 2LL * 512,
        HE1HI, HE1LO, HE1_MP, H0HI, H0LO, H0_MP);

    // 8) SCR = [H1|E0] @ We^T[:,512:1088]  (K=576)
    bf16_gemm<64><<<dim3(1, 80, N_MP), 256, SMEM64>>>(
        HE1HI, HE1LO, HE1_MP, HE1_LD, WTEHI + 512, WTELO + 512, WTE_SL, 1088,
        nullptr, 0, SCR, SCR_MP, 64, 576);
    // 9) R = H0 @ We^T[:,0:512]  (K=512)
    bf16_gemm<64><<<dim3(1, 8, N_MP), 256, SMEM64>>>(
        H0HI, H0LO, H0_MP, 512, WTEHI, WTELO, WTE_SL, 1088,
        nullptr, 0, R, R_MP, 64, 512);

    // 10) layer-1 gate scores
    scores_kernel<<<dim3(N1_ROWS / 4, N_MP), 128>>>(
        R, R_MP, SCR, SCR_MP, b_edge, 2LL * 64,
        v_gate + E_DIM, VG_MP, G2, G2_MP);

    // 11) X2 = [H0 | sum_s G2*H1]
    build_x2_kernel<<<dim3(N1_ROWS, N_MP), 128>>>(
        H0HI, H0LO, H0_MP, HE1HI, HE1LO, HE1_MP, G2, G2_MP, X2HI, X2LO, X2_MP);

    // 12) OUT = relu(X2 @ W_agg[mp,1] + b_agg[mp,1])
    bf16_gemm<128><<<dim3(4, 8, N_MP), 256, SMEM128>>>(
        X2HI, X2LO, X2_MP, 1024, WA1HI, WA1LO, WA1_SL, 1024,
        b_agg + 512, 2LL * 512, OUTB, OUT_MP, 512, 1024);

    // 13) fused attention + FC
    att_final_kernel<<<B_SZ / 16, 256, SMEM_AF>>>(
        OUTB, Wa, ba, va, W_fc, b_fc, out);
}